// round 3
// baseline (speedup 1.0000x reference)
#include <cuda_runtime.h>

#define NB 16
#define NH 16
#define NI 512
#define NE 512
#define IE (NI * NE)
#define JSPLIT 8

// Scratch (device globals; allocations are forbidden)
__device__ float g_embp[JSPLIT][NB * NH * NE];  // 4 MB: emb partials (j-split = 8)
__device__ float g_emb[NB * NH * NE];           // 0.5 MB: folded emb
__device__ float g_part[8][NB * NH * NE];       // 4 MB: GEMM split-K partials

// ---------------------------------------------------------------------------
// Kernel 1: emb[b,h,e] = sum_j x[b,j,e] * W_v[h,j,e]
// Block = 8 b x 8 h x 32 e x 64 j. 256 threads = 32 e-lanes x 8 j-slices.
// Each thread: 8x8 register accumulator; per j: 16 coalesced LDG + 64 FMA.
// Grid = 512 (16 e-chunks x 2 hg x 2 bg x 8 j-splits): 2 resident blocks/SM,
// 1.7 waves -> latency hidden by inter-block overlap (fix for occ=12.5% R2).
// ---------------------------------------------------------------------------
__global__ __launch_bounds__(256) void emb_kernel(const float* __restrict__ x,
                                                  const float* __restrict__ wv) {
    const int t   = threadIdx.x;
    const int el  = t & 31;            // e lane (coalesced)
    const int sl  = t >> 5;            // j slice (warp id) 0..7
    const int bid = blockIdx.x;        // 512 blocks
    const int ec  = bid & 15;          // e chunk 0..15
    const int hg  = (bid >> 4) & 1;    // h half
    const int bg  = (bid >> 5) & 1;    // b half
    const int js  = bid >> 6;          // j split 0..7

    const int e = ec * 32 + el;
    const float* xp = x  + bg * 8 * IE + e;
    const float* wp = wv + hg * 8 * IE + e;

    float acc[8][8];
#pragma unroll
    for (int i = 0; i < 8; ++i)
#pragma unroll
        for (int k = 0; k < 8; ++k) acc[i][k] = 0.f;

    const int j0 = js * 64;
#pragma unroll 2
    for (int jj = 0; jj < 8; ++jj) {
        const int joff = (j0 + sl + jj * 8) * NE;
        float xv[8], wv8[8];
#pragma unroll
        for (int i = 0; i < 8; ++i) xv[i]  = __ldg(xp + i * IE + joff);
#pragma unroll
        for (int k = 0; k < 8; ++k) wv8[k] = __ldg(wp + k * IE + joff);
#pragma unroll
        for (int i = 0; i < 8; ++i)
#pragma unroll
            for (int k = 0; k < 8; ++k)
                acc[i][k] = fmaf(xv[i], wv8[k], acc[i][k]);
    }

    __shared__ float red[8][32][32];   // [slice][ik][el] - conflict-free both ways
    const int b0 = bg * 8, h0 = hg * 8;
#pragma unroll
    for (int half = 0; half < 2; ++half) {
        __syncthreads();
#pragma unroll
        for (int ik = 0; ik < 32; ++ik) {
            const int ikf = half * 32 + ik;
            red[sl][ik][el] = acc[ikf >> 3][ikf & 7];
        }
        __syncthreads();
#pragma unroll
        for (int r = 0; r < 4; ++r) {
            const int ik = r * 8 + sl;
            float s = 0.f;
#pragma unroll
            for (int q = 0; q < 8; ++q) s += red[q][ik][el];
            const int ikf = half * 32 + ik;
            const int b = b0 + (ikf >> 3);
            const int h = h0 + (ikf & 7);
            g_embp[js][(b * NH + h) * NE + e] = s;
        }
    }
}

// ---------------------------------------------------------------------------
// Kernel 1b: fold j-split partials. g_emb = sum_p g_embp[p].
// 4 MB read + 0.5 MB write, ~1 us.
// ---------------------------------------------------------------------------
__global__ __launch_bounds__(256) void fold_kernel() {
    const int idx = blockIdx.x * 256 + threadIdx.x;  // float4 index, 32768 total
    const int o = idx * 4;
    float4 s = *(const float4*)&g_embp[0][o];
#pragma unroll
    for (int p = 1; p < JSPLIT; ++p) {
        const float4 v = *(const float4*)&g_embp[p][o];
        s.x += v.x; s.y += v.y; s.z += v.z; s.w += v.w;
    }
    *(float4*)&g_emb[o] = s;
}

// ---------------------------------------------------------------------------
// Kernel 2: split-K GEMM partials. out[m][n] = sum_k emb[m][k]*w[n][k].
// M=256, N=512, K=512. Tiles 64x64x64, K-split 8 -> 256 blocks.
// ---------------------------------------------------------------------------
__global__ __launch_bounds__(256) void gemm_kernel(const float* __restrict__ w) {
    const int t   = threadIdx.x;
    const int bid = blockIdx.x;        // 256 = 4 mt x 8 nt x 8 kt
    const int kt  = bid & 7;
    const int nt  = (bid >> 3) & 7;
    const int mt  = bid >> 6;
    const int m0 = mt * 64, n0 = nt * 64, k0 = kt * 64;

    __shared__ __align__(16) float sa[64][68];  // [k][m], stride 68: 16B row align
    __shared__ __align__(16) float sb[64][68];  // [k][n]

#pragma unroll
    for (int r = 0; r < 4; ++r) {
        const int lin = t + r * 256;        // 0..1023 float4 slots
        const int row = lin >> 4;           // 0..63
        const int kq  = (lin & 15) * 4;     // 0..60
        const float4 a0 = *(const float4*)&g_emb[(m0 + row) * NE + k0 + kq];
        sa[kq + 0][row] = a0.x;
        sa[kq + 1][row] = a0.y;
        sa[kq + 2][row] = a0.z;
        sa[kq + 3][row] = a0.w;
        const float4 b4 = *(const float4*)&w[(n0 + row) * NE + k0 + kq];
        sb[kq + 0][row] = b4.x;
        sb[kq + 1][row] = b4.y;
        sb[kq + 2][row] = b4.z;
        sb[kq + 3][row] = b4.w;
    }
    __syncthreads();

    const int tx = t & 15;   // n micro-tile
    const int ty = t >> 4;   // m micro-tile
    float acc[4][4];
#pragma unroll
    for (int i = 0; i < 4; ++i)
#pragma unroll
        for (int j = 0; j < 4; ++j) acc[i][j] = 0.f;

#pragma unroll 8
    for (int kk = 0; kk < 64; ++kk) {
        const float4 av = *(const float4*)&sa[kk][ty * 4];
        const float4 bv = *(const float4*)&sb[kk][tx * 4];
        const float a[4] = {av.x, av.y, av.z, av.w};
        const float b[4] = {bv.x, bv.y, bv.z, bv.w};
#pragma unroll
        for (int i = 0; i < 4; ++i)
#pragma unroll
            for (int j = 0; j < 4; ++j)
                acc[i][j] = fmaf(a[i], b[j], acc[i][j]);
    }

#pragma unroll
    for (int i = 0; i < 4; ++i) {
        float4 v;
        v.x = acc[i][0]; v.y = acc[i][1]; v.z = acc[i][2]; v.w = acc[i][3];
        *(float4*)&g_part[kt][(m0 + ty * 4 + i) * NE + n0 + tx * 4] = v;
    }
}

// ---------------------------------------------------------------------------
// Kernel 3: out = sum of 8 split-K partials + bias.
// ---------------------------------------------------------------------------
__global__ __launch_bounds__(256) void finish_kernel(const float* __restrict__ bias,
                                                     float* __restrict__ out) {
    const int idx = blockIdx.x * 256 + threadIdx.x;  // float4 index, 32768 total
    const int o = idx * 4;
    float4 s = *(const float4*)&g_part[0][o];
#pragma unroll
    for (int p = 1; p < 8; ++p) {
        const float4 v = *(const float4*)&g_part[p][o];
        s.x += v.x; s.y += v.y; s.z += v.z; s.w += v.w;
    }
    const float4 bv = *(const float4*)&bias[o & (NE - 1)];
    s.x += bv.x; s.y += bv.y; s.z += bv.z; s.w += bv.w;
    *(float4*)&out[o] = s;
}

extern "C" void kernel_launch(void* const* d_in, const int* in_sizes, int n_in,
                              void* d_out, int out_size) {
    const float* x    = (const float*)d_in[0];  // [16,1,512,512]
    // d_in[1] = W_q, d_in[2] = W_k: mathematically dead (softmax cols sum to 1)
    const float* wv   = (const float*)d_in[3];  // [1,16,512,512]
    const float* mlpw = (const float*)d_in[4];  // [512,512]
    const float* mlpb = (const float*)d_in[5];  // [512]
    float* out = (float*)d_out;                 // [16,16,512]

    emb_kernel<<<512, 256>>>(x, wv);
    fold_kernel<<<128, 256>>>();
    gemm_kernel<<<256, 256>>>(mlpw);
    finish_kernel<<<128, 256>>>(mlpb, out);
}

// round 4
// speedup vs baseline: 1.0987x; 1.0987x over previous
#include <cuda_runtime.h>

#define NB 16
#define NH 16
#define NI 512
#define NE 512
#define IE (NI * NE)
#define JSPLIT 8

// Scratch (device globals; allocations are forbidden)
__device__ float g_embp[JSPLIT][NB * NH * NE];  // 4 MB: emb partials (j-split = 8)

// ---------------------------------------------------------------------------
// Kernel 1: emb[b,h,e] = sum_j x[b,j,e] * W_v[h,j,e]   (j-split partials)
// Also pre-initializes out with the broadcast bias (1 float per thread;
// 512 blocks x 256 threads == 256x512 output elements).
// Block = 8 b x 8 h x 32 e x 64 j. 256 threads = 32 e-lanes x 8 j-slices.
// ---------------------------------------------------------------------------
__global__ __launch_bounds__(256) void emb_kernel(const float* __restrict__ x,
                                                  const float* __restrict__ wv,
                                                  const float* __restrict__ bias,
                                                  float* __restrict__ out) {
    const int t   = threadIdx.x;
    const int bid = blockIdx.x;        // 512 blocks

    // Bias init of the output (gemm_kernel atomically accumulates on top).
    const int oidx = bid * 256 + t;    // 0 .. 131071 == NB*NH*NE
    out[oidx] = bias[oidx & (NE - 1)];

    const int el  = t & 31;            // e lane (coalesced)
    const int sl  = t >> 5;            // j slice (warp id) 0..7
    const int ec  = bid & 15;          // e chunk 0..15
    const int hg  = (bid >> 4) & 1;    // h half
    const int bg  = (bid >> 5) & 1;    // b half
    const int js  = bid >> 6;          // j split 0..7

    const int e = ec * 32 + el;
    const float* xp = x  + bg * 8 * IE + e;
    const float* wp = wv + hg * 8 * IE + e;

    float acc[8][8];
#pragma unroll
    for (int i = 0; i < 8; ++i)
#pragma unroll
        for (int k = 0; k < 8; ++k) acc[i][k] = 0.f;

    const int j0 = js * 64;
#pragma unroll 2
    for (int jj = 0; jj < 8; ++jj) {
        const int joff = (j0 + sl + jj * 8) * NE;
        float xv[8], wv8[8];
#pragma unroll
        for (int i = 0; i < 8; ++i) xv[i]  = __ldg(xp + i * IE + joff);
#pragma unroll
        for (int k = 0; k < 8; ++k) wv8[k] = __ldg(wp + k * IE + joff);
#pragma unroll
        for (int i = 0; i < 8; ++i)
#pragma unroll
            for (int k = 0; k < 8; ++k)
                acc[i][k] = fmaf(xv[i], wv8[k], acc[i][k]);
    }

    __shared__ float red[8][32][32];   // [slice][ik][el] - conflict-free both ways
    const int b0 = bg * 8, h0 = hg * 8;
#pragma unroll
    for (int half = 0; half < 2; ++half) {
        __syncthreads();
#pragma unroll
        for (int ik = 0; ik < 32; ++ik) {
            const int ikf = half * 32 + ik;
            red[sl][ik][el] = acc[ikf >> 3][ikf & 7];
        }
        __syncthreads();
#pragma unroll
        for (int r = 0; r < 4; ++r) {
            const int ik = r * 8 + sl;
            float s = 0.f;
#pragma unroll
            for (int q = 0; q < 8; ++q) s += red[q][ik][el];
            const int ikf = half * 32 + ik;
            const int b = b0 + (ikf >> 3);
            const int h = h0 + (ikf & 7);
            g_embp[js][(b * NH + h) * NE + e] = s;
        }
    }
}

// ---------------------------------------------------------------------------
// Kernel 2: out[m][n] += sum_k emb[m][k]*w[n][k]  (bias already in out)
// M=256, N=512, K=512. Tiles 64x64, split-K=4 (K=128 per block, staged as
// two 64-wide smem chunks to stay under 48KB static smem) -> 128 blocks,
// 1 wave. A-tile load folds the 8 j-split emb partials (removes fold
// kernel). Epilogue: REDG atomicAdd into out (removes finish kernel).
// Per-SM REDG issue (~5.3k cyc) < FMA stream (~8.2k cyc): not binding.
// ---------------------------------------------------------------------------
__global__ __launch_bounds__(256) void gemm_kernel(const float* __restrict__ w,
                                                   float* __restrict__ out) {
    const int t   = threadIdx.x;
    const int bid = blockIdx.x;        // 128 = 4 mt x 8 nt x 4 kt
    const int kt  = bid & 3;
    const int nt  = (bid >> 2) & 7;
    const int mt  = bid >> 5;
    const int m0 = mt * 64, n0 = nt * 64;

    __shared__ __align__(16) float sa[64][68];  // [k][m]
    __shared__ __align__(16) float sb[64][68];  // [k][n]

    const int tx = t & 15;   // n micro-tile
    const int ty = t >> 4;   // m micro-tile
    float acc[4][4];
#pragma unroll
    for (int i = 0; i < 4; ++i)
#pragma unroll
        for (int j = 0; j < 4; ++j) acc[i][j] = 0.f;

#pragma unroll
    for (int kc = 0; kc < 2; ++kc) {
        const int k0 = kt * 128 + kc * 64;
        if (kc) __syncthreads();   // previous chunk's compute done before reload

#pragma unroll
        for (int r = 0; r < 4; ++r) {
            const int lin = t + r * 256;        // 0..1023 float4 slots
            const int row = lin >> 4;           // 0..63
            const int kq  = (lin & 15) * 4;     // 0..60
            const int aoff = (m0 + row) * NE + k0 + kq;
            float4 a = *(const float4*)&g_embp[0][aoff];
#pragma unroll
            for (int p = 1; p < JSPLIT; ++p) {
                const float4 v = *(const float4*)&g_embp[p][aoff];
                a.x += v.x; a.y += v.y; a.z += v.z; a.w += v.w;
            }
            sa[kq + 0][row] = a.x;
            sa[kq + 1][row] = a.y;
            sa[kq + 2][row] = a.z;
            sa[kq + 3][row] = a.w;
            const float4 b4 = *(const float4*)&w[(n0 + row) * NE + k0 + kq];
            sb[kq + 0][row] = b4.x;
            sb[kq + 1][row] = b4.y;
            sb[kq + 2][row] = b4.z;
            sb[kq + 3][row] = b4.w;
        }
        __syncthreads();

#pragma unroll 8
        for (int kk = 0; kk < 64; ++kk) {
            const float4 av = *(const float4*)&sa[kk][ty * 4];
            const float4 bv = *(const float4*)&sb[kk][tx * 4];
            const float a[4] = {av.x, av.y, av.z, av.w};
            const float b[4] = {bv.x, bv.y, bv.z, bv.w};
#pragma unroll
            for (int i = 0; i < 4; ++i)
#pragma unroll
                for (int j = 0; j < 4; ++j)
                    acc[i][j] = fmaf(a[i], b[j], acc[i][j]);
        }
    }

    // Split-K accumulate directly into the bias-initialized output.
#pragma unroll
    for (int i = 0; i < 4; ++i) {
        float* op = &out[(m0 + ty * 4 + i) * NE + n0 + tx * 4];
#pragma unroll
        for (int j = 0; j < 4; ++j)
            atomicAdd(op + j, acc[i][j]);
    }
}

extern "C" void kernel_launch(void* const* d_in, const int* in_sizes, int n_in,
                              void* d_out, int out_size) {
    const float* x    = (const float*)d_in[0];  // [16,1,512,512]
    // d_in[1] = W_q, d_in[2] = W_k: mathematically dead (softmax cols sum to 1)
    const float* wv   = (const float*)d_in[3];  // [1,16,512,512]
    const float* mlpw = (const float*)d_in[4];  // [512,512]
    const float* mlpb = (const float*)d_in[5];  // [512]
    float* out = (float*)d_out;                 // [16,16,512]

    emb_kernel<<<512, 256>>>(x, wv, mlpb, out);
    gemm_kernel<<<128, 256>>>(mlpw, out);
}